// round 17
// baseline (speedup 1.0000x reference)
#include <cuda_runtime.h>
#include <cuda_fp16.h>
#include <cstdint>

// Problem constants
#define B_    128
#define A_    30
#define T_    65
#define FIN_  4
#define H_    1920
#define G4_   7680
#define NSTEP 64

// GEMM tiling: CTA tile 128(M) x 64(N), K chunk = 64 fp16
#define KCHUNKS  30
#define NSTG     4
#define STAGE_B  24576              // A 16K + W 8K
#define SMEMB    (1024 + 1024 + NSTG * STAGE_B)
#define LOFF     14745600u
#define GSLICE   (B_ * G4_)
#define TOT_IH   (2 * G4_ * H_)
#define TOT_W3   (H_ * H_)

// ---------------- device scratch ----------------
__device__ __align__(1024) __half g_wih[2u*7680u*1920u];
__device__ __align__(1024) __half g_whh[2u*7680u*1920u];
__device__ __align__(1024) __half g_w3[1920u*1920u];
__device__ __align__(1024) __half g_x[245760];
__device__ __align__(1024) __half g_h0[245760];
__device__ __align__(1024) __half g_h1[245760];
__device__ float g_c[2 * B_ * H_];
__device__ float g_gx[GSLICE];
__device__ float g_gx1[2 * GSLICE];
__device__ float g_gh0[2 * GSLICE];
__device__ float g_gh1[2 * GSLICE];
__device__ float g_r3[2 * B_ * H_];
__device__ unsigned g_ctr[4];      // 0=r3done, 1=xdone, 2=gh0done, 3=gh1done

// ---------------- PTX helpers ----------------
__device__ __forceinline__ uint32_t smem_u32(const void* p) {
    uint32_t a;
    asm("{ .reg .u64 t; cvta.to.shared.u64 t, %1; cvt.u32.u64 %0, t; }" : "=r"(a) : "l"(p));
    return a;
}
#define MBAR_INIT(addr, cnt) \
    asm volatile("mbarrier.init.shared.b64 [%0], %1;" :: "r"(addr), "r"((uint32_t)(cnt)) : "memory")
#define MBAR_EXPECT_TX(addr, bytes) \
    asm volatile("mbarrier.arrive.expect_tx.shared.b64 _, [%0], %1;" :: "r"(addr), "r"((uint32_t)(bytes)) : "memory")
#define MBAR_ARRIVE(addr) \
    asm volatile("mbarrier.arrive.shared.b64 _, [%0];" :: "r"(addr) : "memory")
#define MBAR_WAIT(addr, par) do { \
    uint32_t _m=(addr), _p=(par), _d; \
    asm volatile("{\n\t.reg .pred p;\n\tmbarrier.try_wait.parity.acquire.cta.shared::cta.b64 p, [%1], %2;\n\tselp.b32 %0,1,0,p;\n\t}" \
        : "=r"(_d) : "r"(_m), "r"(_p) : "memory"); \
    if (!_d) { \
        asm volatile("{\n\t.reg .pred P1;\n\tWL_%=:\n\tmbarrier.try_wait.parity.acquire.cta.shared::cta.b64 P1, [%0], %1, 0x989680;\n\t@P1 bra.uni WD_%=;\n\tbra.uni WL_%=;\n\tWD_%=:\n\t}" \
            :: "r"(_m), "r"(_p) : "memory"); \
    } } while (0)
#define BULK_G2S(dst, src, bytes, mbar) \
    asm volatile("cp.async.bulk.shared::cluster.global.mbarrier::complete_tx::bytes [%0], [%1], %2, [%3];" \
        :: "r"(dst), "l"(src), "r"((uint32_t)(bytes)), "r"(mbar) : "memory")

#define LDSM4(r, addr) \
    asm volatile("ldmatrix.sync.aligned.m8n8.x4.shared.b16 {%0,%1,%2,%3}, [%4];" \
        : "=r"((r)[0]), "=r"((r)[1]), "=r"((r)[2]), "=r"((r)[3]) : "r"(addr))
#define MMA(d, a, b0v, b1v) \
    asm volatile("mma.sync.aligned.m16n8k16.row.col.f32.f16.f16.f32 " \
        "{%0,%1,%2,%3}, {%4,%5,%6,%7}, {%8,%9}, {%0,%1,%2,%3};" \
        : "+f"((d)[0]), "+f"((d)[1]), "+f"((d)[2]), "+f"((d)[3]) \
        : "r"((a)[0]), "r"((a)[1]), "r"((a)[2]), "r"((a)[3]), "r"(b0v), "r"(b1v))

__device__ __forceinline__ uint32_t sw128(uint32_t o) { return o ^ ((o >> 3) & 0x70); }
__device__ __forceinline__ uint32_t act_idx(int row, int k) {
    return (uint32_t)((k >> 6) * 8192) + (sw128((uint32_t)(row * 128 + (k & 63) * 2)) >> 1);
}
__device__ __forceinline__ void ctr_spin(const unsigned* ctr, unsigned tgt) {
    while (*(volatile const unsigned*)ctr < tgt) __nanosleep(64);
    __threadfence();
}

// ---------------- merged weight conversion ----------------
__global__ void __launch_bounds__(256) conv_all(
    const float* __restrict__ Wih, const float* __restrict__ Whh, const float* __restrict__ W3s,
    __half* __restrict__ wih, __half* __restrict__ whh, __half* __restrict__ w3)
{
    int i = blockIdx.x * 256 + threadIdx.x;
    const float* src; __half* dst; int local;
    if (i < TOT_IH)               { src = Wih; dst = wih; local = i; }
    else if (i < 2 * TOT_IH)      { src = Whh; dst = whh; local = i - TOT_IH; }
    else if (i < 2 * TOT_IH + TOT_W3) { src = W3s; dst = w3; local = i - 2 * TOT_IH; }
    else return;
    int n = local / H_, k = local - n * H_;
    uint32_t d = (uint32_t)((n >> 6) * KCHUNKS + (k >> 6)) * 4096
               + (sw128((uint32_t)((n & 63) * 128 + (k & 63) * 2)) >> 1);
    dst[d] = __float2half(src[local]);
}

// ---------------- GEMM core: W pre-sync prefetch; optional trigger/spin/bump ----------------
__device__ __forceinline__ void gemm_core(
    float* C, int ldc,
    const __half* A, const __half* W,
    const float* bias0, const float* bias1,
    int ccnt, int cbeg, int nt,
    int earlyTrig, const unsigned* waitCtr, unsigned waitTgt, unsigned* bumpCtr)
{
    extern __shared__ char smraw[];
    char* sm = (char*)(((unsigned long long)smraw + 1023ull) & ~1023ull);
    const uint32_t sb = smem_u32(sm);
    const uint32_t FULL = sb;
    const uint32_t DONE = sb + 64;
    const uint32_t STG0 = sb + 1024;

    const int tid = threadIdx.x;
    const int wid = tid >> 5, lane = tid & 31;
    const int wm = (wid & 3) * 32;
    const int wn = (wid >> 2) * 32;

    if (tid == 0) {
        for (int s = 0; s < NSTG; s++) { MBAR_INIT(FULL + 8 * s, 1); MBAR_INIT(DONE + 8 * s, 8); }
        asm volatile("fence.proxy.async.shared::cta;" ::: "memory");
    }
    __syncthreads();

    // prefetch static W for prologue stages BEFORE predecessor wait
    if (tid == 0) {
        for (int c = 0; c < NSTG && c < ccnt; c++) {
            int k = cbeg + c;
            uint32_t st = STG0 + c * STAGE_B;
            MBAR_EXPECT_TX(FULL + 8 * c, STAGE_B);
            BULK_G2S(st + 16384, W + ((size_t)nt * KCHUNKS + k) * 4096, 8192, FULL + 8 * c);
        }
    }

    cudaGridDependencySynchronize();
    if (earlyTrig) cudaTriggerProgrammaticLaunchCompletion();

    if (tid == 0) {
        if (waitCtr) ctr_spin(waitCtr, waitTgt);
        for (int c = 0; c < NSTG && c < ccnt; c++) {
            int k = cbeg + c;
            uint32_t st = STG0 + c * STAGE_B;
            BULK_G2S(st, A + (size_t)k * 8192, 16384, FULL + 8 * c);
        }
    }

    float acc[2][4][4];
#pragma unroll
    for (int i = 0; i < 2; i++)
#pragma unroll
        for (int jn = 0; jn < 4; jn++)
#pragma unroll
            for (int q = 0; q < 4; q++) acc[i][jn][q] = 0.f;

    const int a_row  = (lane & 7) + ((lane >> 3) & 1) * 8;
    const int a_koff = (lane >> 4) * 16;
    const int w_row  = (lane & 7) + ((lane >> 4) << 3);
    const int w_koff = ((lane >> 3) & 1) * 16;

    for (int c = 0; c < ccnt; c++) {
        int s = c & (NSTG - 1);
        MBAR_WAIT(FULL + 8 * s, (c >> 2) & 1);
        uint32_t stg = STG0 + s * STAGE_B;

#pragma unroll
        for (int kb = 0; kb < 4; kb++) {
            uint32_t av[2][4], wv[2][4];
#pragma unroll
            for (int mt = 0; mt < 2; mt++) {
                uint32_t ad = stg + sw128((uint32_t)((wm + mt * 16 + a_row) * 128 + kb * 32 + a_koff));
                LDSM4(av[mt], ad);
            }
#pragma unroll
            for (int hf = 0; hf < 2; hf++) {
                uint32_t wd = stg + 16384 + sw128((uint32_t)((wn + hf * 16 + w_row) * 128 + kb * 32 + w_koff));
                LDSM4(wv[hf], wd);
            }
#pragma unroll
            for (int mt = 0; mt < 2; mt++) {
#pragma unroll
                for (int hf = 0; hf < 2; hf++) {
                    MMA(acc[mt][2 * hf],     av[mt], wv[hf][0], wv[hf][1]);
                    MMA(acc[mt][2 * hf + 1], av[mt], wv[hf][2], wv[hf][3]);
                }
            }
        }
        __syncwarp();
        if (lane == 0) MBAR_ARRIVE(DONE + 8 * s);

        int ncn = c + NSTG;
        if (tid == 0 && ncn < ccnt) {
            MBAR_WAIT(DONE + 8 * s, (c >> 2) & 1);
            int k = cbeg + ncn;
            uint32_t st = STG0 + s * STAGE_B;
            MBAR_EXPECT_TX(FULL + 8 * s, STAGE_B);
            BULK_G2S(st,         A + (size_t)k * 8192, 16384, FULL + 8 * s);
            BULK_G2S(st + 16384, W + ((size_t)nt * KCHUNKS + k) * 4096, 8192, FULL + 8 * s);
        }
    }

#pragma unroll
    for (int mt = 0; mt < 2; mt++) {
        int r0 = wm + mt * 16 + (lane >> 2);
        float* cp = C + (size_t)r0 * ldc;
#pragma unroll
        for (int ng = 0; ng < 4; ng++) {
            int col = nt * 64 + wn + ng * 8 + 2 * (lane & 3);
            float b0v = 0.f, b1v = 0.f;
            if (bias0) { b0v = bias0[col] + bias1[col]; b1v = bias0[col + 1] + bias1[col + 1]; }
            *(float2*)(cp + col) = make_float2(acc[mt][ng][0] + b0v, acc[mt][ng][1] + b1v);
            *(float2*)(cp + 8 * ldc + col) = make_float2(acc[mt][ng][2] + b0v, acc[mt][ng][3] + b1v);
        }
    }

    if (bumpCtr) {
        __threadfence();
        __syncthreads();
        if (tid == 0) atomicAdd(bumpCtr, 1u);
    }
}

// ---------------- K_A2: x@Wih0 full-K with biases; spins on x-ready counter ----------------
__global__ void __launch_bounds__(256, 1) gemm_single(
    float* __restrict__ C, int ldc,
    const __half* __restrict__ A, const __half* __restrict__ W,
    const float* __restrict__ bias0, const float* __restrict__ bias1, unsigned xTgt)
{
    gemm_core(C, ldc, A, W, bias0, bias1, KCHUNKS, 0, blockIdx.x,
              0, &g_ctr[1], xTgt, nullptr);
}

// ---------------- comboA: {h0@Wih1 -> gx1 (240), h0@Whh0 -> gh0 (240, bumps gh0ctr)} ----------------
__global__ void __launch_bounds__(256, 1) gemm_comboA(
    const __half* __restrict__ h0,
    const __half* __restrict__ wih1, const __half* __restrict__ whh0,
    float* __restrict__ gx1, float* __restrict__ gh0,
    const float* __restrict__ bih1, const float* __restrict__ bhh1,
    int doGh)
{
    int bid = blockIdx.x;
    if (bid < 240) {
        int slice = bid / 120, nt = bid - slice * 120;
        const float* b0 = (slice == 0) ? bih1 : nullptr;
        const float* b1 = (slice == 0) ? bhh1 : nullptr;
        gemm_core(gx1 + (size_t)slice * GSLICE, G4_, h0, wih1, b0, b1, 15, slice * 15, nt,
                  0, nullptr, 0, nullptr);
    } else {
        if (!doGh) return;
        int b = bid - 240;
        int slice = b / 120, nt = b - slice * 120;
        gemm_core(gh0 + (size_t)slice * GSLICE, G4_, h0, whh0, nullptr, nullptr, 15, slice * 15, nt,
                  0, nullptr, 0, &g_ctr[2]);
    }
}

// ---------------- r3K: h1@W3 (60 CTAs), early trigger, bumps r3ctr ----------------
__global__ void __launch_bounds__(256, 1) gemm_r3(
    const __half* __restrict__ h1, const __half* __restrict__ w3, float* __restrict__ r3)
{
    int slice = blockIdx.x / 30, nt = blockIdx.x - slice * 30;
    gemm_core(r3 + (size_t)slice * B_ * H_, H_, h1, w3, nullptr, nullptr, 15, slice * 15, nt,
              1, nullptr, 0, &g_ctr[0]);
}

// ---------------- gh1K: h1@Whh1 (240 CTAs), early trigger, bumps gh1ctr ----------------
__global__ void __launch_bounds__(256, 1) gemm_gh1(
    const __half* __restrict__ h1, const __half* __restrict__ whh1, float* __restrict__ gh1)
{
    int slice = blockIdx.x / 120, nt = blockIdx.x - slice * 120;
    gemm_core(gh1 + (size_t)slice * GSLICE, G4_, h1, whh1, nullptr, nullptr, 15, slice * 15, nt,
              1, nullptr, 0, &g_ctr[3]);
}

// ---------------- LSTM cell: x2 vectorized, 480 blocks; spins on gh counter ----------------
__global__ void __launch_bounds__(256) lstm_cell(
    const float* __restrict__ gx, const float* __restrict__ gh,
    float* __restrict__ c, __half* __restrict__ h, int twoGx,
    const unsigned* __restrict__ ghCtr, unsigned ghTgt)
{
    cudaGridDependencySynchronize();
    if (threadIdx.x == 0 && ghTgt) ctr_spin(ghCtr, ghTgt);
    __syncthreads();

    int idx2 = (blockIdx.x * 256 + threadIdx.x) * 2;
    int b = idx2 / H_;
    int jj = idx2 - b * H_;
    const float* px = gx + b * G4_;
    const float* px2 = gx + GSLICE + b * G4_;
    const float* p0 = gh + b * G4_;
    const float* p1 = gh + GSLICE + b * G4_;

    float igs[2], fgs[2], ggs[2], ogs[2];
    {
        float2 xi = *(const float2*)(px + jj),           hi0 = *(const float2*)(p0 + jj),           hi1 = *(const float2*)(p1 + jj);
        float2 xf = *(const float2*)(px + H_ + jj),      hf0 = *(const float2*)(p0 + H_ + jj),      hf1 = *(const float2*)(p1 + H_ + jj);
        float2 xg = *(const float2*)(px + 2 * H_ + jj),  hg0 = *(const float2*)(p0 + 2 * H_ + jj),  hg1 = *(const float2*)(p1 + 2 * H_ + jj);
        float2 xo = *(const float2*)(px + 3 * H_ + jj),  ho0 = *(const float2*)(p0 + 3 * H_ + jj),  ho1 = *(const float2*)(p1 + 3 * H_ + jj);
        igs[0] = xi.x + hi0.x + hi1.x; igs[1] = xi.y + hi0.y + hi1.y;
        fgs[0] = xf.x + hf0.x + hf1.x; fgs[1] = xf.y + hf0.y + hf1.y;
        ggs[0] = xg.x + hg0.x + hg1.x; ggs[1] = xg.y + hg0.y + hg1.y;
        ogs[0] = xo.x + ho0.x + ho1.x; ogs[1] = xo.y + ho0.y + ho1.y;
    }
    if (twoGx) {
        float2 xi = *(const float2*)(px2 + jj);
        float2 xf = *(const float2*)(px2 + H_ + jj);
        float2 xg = *(const float2*)(px2 + 2 * H_ + jj);
        float2 xo = *(const float2*)(px2 + 3 * H_ + jj);
        igs[0] += xi.x; igs[1] += xi.y;
        fgs[0] += xf.x; fgs[1] += xf.y;
        ggs[0] += xg.x; ggs[1] += xg.y;
        ogs[0] += xo.x; ogs[1] += xo.y;
    }
    float2 cv = *(const float2*)(c + idx2);
    float cvs[2] = { cv.x, cv.y };
    float hn[2], cn[2];
#pragma unroll
    for (int q = 0; q < 2; q++) {
        float si = 1.f / (1.f + expf(-igs[q]));
        float sf = 1.f / (1.f + expf(-fgs[q]));
        float so = 1.f / (1.f + expf(-ogs[q]));
        float tg = tanhf(ggs[q]);
        cn[q] = sf * cvs[q] + si * tg;
        hn[q] = so * tanhf(cn[q]);
    }
    *(float2*)(c + idx2) = make_float2(cn[0], cn[1]);

    __half2 a2 = __floats2half2_rn(hn[0], hn[1]);
    uint32_t byteoff = (uint32_t)(jj >> 6) * 16384 + sw128((uint32_t)(b * 128 + (jj & 63) * 2));
    *(uint32_t*)((char*)h + byteoff) = *(uint32_t*)&a2;
}

// ---------------- tail: spins r3ctr; early-trigger; bumps xctr after writing x ----------------
__global__ void __launch_bounds__(256) tail_kernel(
    const float* __restrict__ r3, const float* __restrict__ b3,
    const float* __restrict__ W4, const float* __restrict__ b4,
    const float* __restrict__ inputs, float* __restrict__ out,
    __half* __restrict__ x,
    const float* __restrict__ W1, const float* __restrict__ b1,
    const float* __restrict__ W2, const float* __restrict__ b2,
    int t, int produce, const int* __restrict__ burn, int do_w4)
{
    __shared__ __align__(16) float xs[H_];
    __shared__ float part[240];
    __shared__ float outs[A_ * FIN_];
    __shared__ float W1t[4 * 64];
    __shared__ float W2t[64 * 64];
    __shared__ float b1s[64], b2s[64];
    __shared__ float ins_s[A_ * FIN_];
    __shared__ float x1s[A_ * 64];

    const int b = blockIdx.x, tid = threadIdx.x;

    // dependency-free: stage MLP weights
    for (int i = tid; i < 64 * 64; i += 256) {
        int jj = i >> 6, kk = i & 63;
        W2t[kk * 64 + jj] = W2[i];
    }
    if (tid < 256) {
        int jj = tid >> 2, ff = tid & 3;
        W1t[ff * 64 + jj] = W1[tid];
    }
    if (tid < 64) { b1s[tid] = b1[tid]; b2s[tid] = b2[tid]; }

    cudaGridDependencySynchronize();
    cudaTriggerProgrammaticLaunchCompletion();

    const int bi = burn ? *burn : 20;

    if (do_w4) {
        if (tid == 0) ctr_spin(&g_ctr[0], 60u * (unsigned)(t + 1));
        __syncthreads();
        for (int k = tid; k < H_; k += 256)
            xs[k] = fmaxf(r3[b * H_ + k] + r3[(B_ + b) * H_ + k] + b3[k], 0.f);
        __syncthreads();
        if (tid < 240) {
            int o = tid % 120, half = tid / 120;
            const float4* wp = (const float4*)(W4 + (size_t)o * H_ + half * 960);
            const float4* xp = (const float4*)(xs + half * 960);
            float a0 = 0.f, a1 = 0.f, a2 = 0.f, a3 = 0.f;
#pragma unroll 4
            for (int k = 0; k < 240; k++) {
                float4 w = wp[k]; float4 xv = xp[k];
                a0 = fmaf(w.x, xv.x, a0); a1 = fmaf(w.y, xv.y, a1);
                a2 = fmaf(w.z, xv.z, a2); a3 = fmaf(w.w, xv.w, a3);
            }
            part[tid] = (a0 + a1) + (a2 + a3);
        }
        __syncthreads();
        if (tid < A_ * FIN_) {
            float acc = b4[tid] + part[tid] + part[tid + 120];
            int a = tid >> 2, f = tid & 3;
            int r = b * A_ + a;
            float insv = (t <= bi) ? inputs[(r * T_ + t) * FIN_ + f]
                                   : out[(r * NSTEP + t - 1) * FIN_ + f];
            float ov = acc + insv;
            out[(r * NSTEP + t) * FIN_ + f] = ov;
            outs[tid] = ov;
        }
        __syncthreads();
    }

    if (produce >= NSTEP) return;

    if (tid < A_ * FIN_) {
        int a = tid >> 2, f = tid & 3;
        int r = b * A_ + a;
        ins_s[tid] = (produce <= bi) ? inputs[(r * T_ + produce) * FIN_ + f] : outs[tid];
    }
    __syncthreads();

    for (int idx = tid; idx < A_ * 64; idx += 256) {
        int a = idx >> 6, j = idx & 63;
        float v = b1s[j];
#pragma unroll
        for (int f = 0; f < 4; f++) v = fmaf(ins_s[a * 4 + f], W1t[f * 64 + j], v);
        x1s[idx] = fmaxf(v, 0.f);
    }
    __syncthreads();

    for (int idx = tid; idx < A_ * 64; idx += 256) {
        int a = idx >> 6, j = idx & 63;
        float v = b2s[j];
        const float* x1p = x1s + a * 64;
#pragma unroll
        for (int k = 0; k < 64; k++) v = fmaf(x1p[k], W2t[k * 64 + j], v);
        v = fmaxf(v, 0.f);
        x[act_idx(b, a * 64 + j)] = __float2half(v);
    }

    // publish x for this CTA's batch row
    __threadfence();
    __syncthreads();
    if (tid == 0) atomicAdd(&g_ctr[1], 1u);
}

// ---------------- launch ----------------
extern "C" void kernel_launch(void* const* d_in, const int* in_sizes, int n_in,
                              void* d_out, int out_size)
{
    const float* inputs = (const float*)d_in[0];
    const float* W1  = (const float*)d_in[1];
    const float* b1  = (const float*)d_in[2];
    const float* W2  = (const float*)d_in[3];
    const float* b2  = (const float*)d_in[4];
    const float* Wih = (const float*)d_in[5];
    const float* Whh = (const float*)d_in[6];
    const float* bih = (const float*)d_in[7];
    const float* bhh = (const float*)d_in[8];
    const float* W3  = (const float*)d_in[9];
    const float* b3  = (const float*)d_in[10];
    const float* W4  = (const float*)d_in[11];
    const float* b4  = (const float*)d_in[12];
    const int* burn  = (n_in > 14) ? (const int*)d_in[14] : nullptr;
    float* out = (float*)d_out;

    cudaFuncSetAttribute(gemm_single, cudaFuncAttributeMaxDynamicSharedMemorySize, SMEMB);
    cudaFuncSetAttribute(gemm_comboA, cudaFuncAttributeMaxDynamicSharedMemorySize, SMEMB);
    cudaFuncSetAttribute(gemm_r3,     cudaFuncAttributeMaxDynamicSharedMemorySize, SMEMB);
    cudaFuncSetAttribute(gemm_gh1,    cudaFuncAttributeMaxDynamicSharedMemorySize, SMEMB);

    void *pwih, *pwhh, *pw3, *px, *ph0, *ph1, *pc, *pgx, *pgx1, *pgh0, *pgh1, *pr, *pctr;
    cudaGetSymbolAddress(&pwih, g_wih);
    cudaGetSymbolAddress(&pwhh, g_whh);
    cudaGetSymbolAddress(&pw3, g_w3);
    cudaGetSymbolAddress(&px, g_x);
    cudaGetSymbolAddress(&ph0, g_h0);
    cudaGetSymbolAddress(&ph1, g_h1);
    cudaGetSymbolAddress(&pc, g_c);
    cudaGetSymbolAddress(&pgx, g_gx);
    cudaGetSymbolAddress(&pgx1, g_gx1);
    cudaGetSymbolAddress(&pgh0, g_gh0);
    cudaGetSymbolAddress(&pgh1, g_gh1);
    cudaGetSymbolAddress(&pr, g_r3);
    cudaGetSymbolAddress(&pctr, g_ctr);

    __half *wih = (__half*)pwih, *whh = (__half*)pwhh, *w3 = (__half*)pw3;
    __half *x = (__half*)px, *h0 = (__half*)ph0, *h1 = (__half*)ph1;
    float* c0 = (float*)pc;
    float* gx = (float*)pgx;
    float* gx1 = (float*)pgx1;
    float* gh0 = (float*)pgh0;
    float* gh1 = (float*)pgh1;
    float* r3 = (float*)pr;

    // zero state + counters (all in-graph for replay determinism)
    cudaMemsetAsync(pc, 0, sizeof(float) * 2 * B_ * H_);
    cudaMemsetAsync(ph0, 0, sizeof(__half) * 245760);
    cudaMemsetAsync(ph1, 0, sizeof(__half) * 245760);
    cudaMemsetAsync(pgh0, 0, sizeof(float) * 2 * GSLICE);
    cudaMemsetAsync(pgh1, 0, sizeof(float) * 2 * GSLICE);
    cudaMemsetAsync(pctr, 0, sizeof(unsigned) * 4);

    // PDL launch config
    cudaLaunchAttribute pdlAttr[1];
    pdlAttr[0].id = cudaLaunchAttributeProgrammaticStreamSerialization;
    pdlAttr[0].val.programmaticStreamSerializationAllowed = 1;
    auto mkcfg = [&](unsigned grid, unsigned block, size_t smem) {
        cudaLaunchConfig_t cfg = {};
        cfg.gridDim = dim3(grid, 1, 1);
        cfg.blockDim = dim3(block, 1, 1);
        cfg.dynamicSmemBytes = smem;
        cfg.stream = 0;
        cfg.attrs = pdlAttr;
        cfg.numAttrs = 1;
        return cfg;
    };

    const int TOTAL_CONV = 2 * TOT_IH + TOT_W3;
    conv_all<<<(TOTAL_CONV + 255) / 256, 256>>>(Wih, Whh, W3, wih, whh, w3);

    // initial MLP (produce x for t=0; bumps xctr to 128)
    {
        cudaLaunchConfig_t cfg = mkcfg(B_, 256, 0);
        cudaLaunchKernelEx(&cfg, tail_kernel,
            (const float*)r3, b3, W4, b4, inputs, out, x,
            W1, b1, W2, b2, 0, 0, burn, 0);
    }

    for (int t = 0; t < NSTEP; t++) {
        int last = (t + 1 >= NSTEP);
        // K_A2: gx = x(t)@Wih0 + biases (launches on tail trigger; spins xctr)
        {
            cudaLaunchConfig_t cfg = mkcfg(120, 256, SMEMB);
            cudaLaunchKernelEx(&cfg, gemm_single, gx, (int)G4_,
                (const __half*)x, (const __half*)wih, bih, bhh,
                (unsigned)(128 * (t + 1)));
        }
        // cell0: gx + gh0(2 slices) -> c0, h0 (spins gh0ctr from prior comboA)
        {
            cudaLaunchConfig_t cfg = mkcfg(480, 256, 0);
            cudaLaunchKernelEx(&cfg, lstm_cell,
                (const float*)gx, (const float*)gh0, c0, h0, 0,
                (const unsigned*)&(((unsigned*)pctr)[2]), (unsigned)(240 * t));
        }
        // comboA: pooled {h0@Wih1 -> gx1, h0@Whh0 -> gh0 (for t+1, bumps gh0ctr)}
        {
            cudaLaunchConfig_t cfg = mkcfg(480, 256, SMEMB);
            cudaLaunchKernelEx(&cfg, gemm_comboA,
                (const __half*)h0, (const __half*)(wih + LOFF), (const __half*)whh,
                gx1, gh0, bih + G4_, bhh + G4_, (int)(!last));
        }
        // cell1: gx1(2) + gh1(2) -> c1, h1 (spins gh1ctr from prior gh1K)
        {
            cudaLaunchConfig_t cfg = mkcfg(480, 256, 0);
            cudaLaunchKernelEx(&cfg, lstm_cell,
                (const float*)gx1, (const float*)gh1, c0 + B_ * H_, h1, 1,
                (const unsigned*)&(((unsigned*)pctr)[3]), (unsigned)(240 * t));
        }
        // r3K: h1@W3 -> r3 (60 CTAs, early trigger, bumps r3ctr)
        {
            cudaLaunchConfig_t cfg = mkcfg(60, 256, SMEMB);
            cudaLaunchKernelEx(&cfg, gemm_r3, (const __half*)h1, (const __half*)w3, r3);
        }
        // gh1K: h1@Whh1 -> gh1 for t+1 (240, early trigger, bumps gh1ctr); skip at last step
        if (!last) {
            cudaLaunchConfig_t cfg = mkcfg(240, 256, SMEMB);
            cudaLaunchKernelEx(&cfg, gemm_gh1, (const __half*)h1,
                (const __half*)(whh + LOFF), gh1);
        }
        // tail: spins r3ctr; W4 + residual + out, then MLP for t+1 (bumps xctr)
        {
            cudaLaunchConfig_t cfg = mkcfg(B_, 256, 0);
            cudaLaunchKernelEx(&cfg, tail_kernel,
                (const float*)r3, b3, W4, b4, inputs, out, x,
                W1, b1, W2, b2, t, t + 1, burn, 1);
        }
    }
}